// round 11
// baseline (speedup 1.0000x reference)
#include <cuda_runtime.h>
#include <cuda_fp16.h>

#define NN 100000
#define DD 64
#define HD 32   // half2 elements per node row
#define EE 1200000
#define SCAN_CHUNK 1024
#define NBLK_SCAN ((NN + SCAN_CHUNK - 1) / SCAN_CHUNK)  // 98

// ---------------- scratch (static device globals — allowed) ----------------
__device__ int     g_deg[NN];      // col-degree
__device__ int     g_cnt[NN];      // row counts for CSR
__device__ int     g_rowptr[NN];   // exclusive scan of g_cnt
__device__ int     g_cursor[NN];   // placement cursors (pre-seeded)
__device__ float   g_invsq[NN];    // rsqrt(max(deg,1))
__device__ int     g_aggr[NBLK_SCAN];          // per-block aggregates
__device__ volatile int g_ready[NBLK_SCAN];    // publish flags (re-zeroed each call)
__device__ int     g_col[EE];      // col only, sorted by row
__device__ __half2 g_x0[NN * HD];  // pre-scaled features: invsq[node]*x[node]
__device__ __half2 g_x1[NN * HD];
__device__ __half2 g_out[NN * HD]; // running residual sum (fp16)
__device__ int     g_is64;

// ---------------- init + dtype detect (block 0 samples the edge array) ----------------
// For nonnegative int64 < 2^31, every odd 32-bit word (high half) is 0.
__global__ void initdet_k(const unsigned* __restrict__ ei_words) {
    int i = blockIdx.x * blockDim.x + threadIdx.x;
    if (i < NN) {
        g_deg[i] = 0;
        g_cnt[i] = 0;
    }
    if (i < NBLK_SCAN) g_ready[i] = 0;   // reset lookback flags every call
    if (blockIdx.x == 0) {
        __shared__ int nz;
        if (threadIdx.x == 0) nz = 0;
        __syncthreads();
        int cnt = 0;
        const int S = 8192;
        const int stride = (2 * EE) / S;
        for (int s = threadIdx.x; s < S; s += blockDim.x) {
            long long idx = ((long long)s * stride) | 1;  // odd 32-bit word
            if (ei_words[idx] != 0u) cnt++;
        }
        atomicAdd(&nz, cnt);
        __syncthreads();
        if (threadIdx.x == 0) g_is64 = (nz == 0) ? 1 : 0;
    }
}

__device__ __forceinline__ int edge_val(const void* ei, long long idx) {
    if (g_is64) return (int)((const long long*)ei)[idx];
    return ((const int*)ei)[idx];
}

// ---------------- histograms: col-degree + row counts ----------------
__global__ void hist_k(const void* __restrict__ ei) {
    int e = blockIdx.x * blockDim.x + threadIdx.x;
    if (e >= EE) return;
    int r = edge_val(ei, e);
    int c = edge_val(ei, (long long)EE + e);
    atomicAdd(&g_deg[c], 1);
    atomicAdd(&g_cnt[r], 1);
}

// ---------------- fused single-pass scan (decoupled lookback) ----------------
// 98 blocks, all co-resident on the chip -> polling predecessors is deadlock-free.
// Produces rowptr (exclusive scan of cnt), seeds cursor, computes invsq.
__global__ void scanfused_k() {
    __shared__ int wsum[32];
    __shared__ int pred[128];
    int bid = blockIdx.x;
    int g = bid * SCAN_CHUNK + threadIdx.x;
    int v = (g < NN) ? g_cnt[g] : 0;
    int lane = threadIdx.x & 31, wid = threadIdx.x >> 5;

    // block-local inclusive scan (warp shuffles)
    int x = v;
#pragma unroll
    for (int off = 1; off < 32; off <<= 1) {
        int t = __shfl_up_sync(0xffffffffu, x, off);
        if (lane >= off) x += t;
    }
    if (lane == 31) wsum[wid] = x;
    __syncthreads();
    if (wid == 0) {
        int s = wsum[lane];
#pragma unroll
        for (int off = 1; off < 32; off <<= 1) {
            int t = __shfl_up_sync(0xffffffffu, s, off);
            if (lane >= off) s += t;
        }
        wsum[lane] = s;
    }
    __syncthreads();
    int incl = x + (wid ? wsum[wid - 1] : 0);

    // publish this block's aggregate
    if (threadIdx.x == SCAN_CHUNK - 1) {
        g_aggr[bid] = incl;
        __threadfence();
        g_ready[bid] = 1;
    }

    // parallel lookback: thread t polls predecessor t's aggregate
    if (threadIdx.x < 128) {
        int a = 0;
        if (threadIdx.x < bid) {
            while (g_ready[threadIdx.x] == 0) { }
            __threadfence();
            a = g_aggr[threadIdx.x];
        }
        pred[threadIdx.x] = a;
    }
    __syncthreads();
    if (threadIdx.x < 64) pred[threadIdx.x] += pred[threadIdx.x + 64];
    __syncthreads();
    if (threadIdx.x < 32) {
        int s = pred[threadIdx.x] + pred[threadIdx.x + 32];
#pragma unroll
        for (int m = 16; m; m >>= 1) s += __shfl_xor_sync(0xffffffffu, s, m);
        if (threadIdx.x == 0) pred[0] = s;
    }
    __syncthreads();
    int offset = pred[0];

    if (g < NN) {
        int p = incl - v + offset;   // global exclusive prefix
        g_rowptr[g] = p;
        g_cursor[g] = p;
        g_invsq[g] = rsqrtf(fmaxf((float)g_deg[g], 1.0f));
    }
}

// ---------------- scale: x0 = half(invsq[node] * emb) ----------------
__global__ void scale_k(const float* __restrict__ emb) {
    int i = blockIdx.x * blockDim.x + threadIdx.x;
    if (i >= NN * HD) return;
    float isr = g_invsq[i >> 5];
    float2 e = ((const float2*)emb)[i];
    g_x0[i] = __floats2half2_rn(e.x * isr, e.y * isr);
}

// ---------------- place edges into CSR (col only; norm folded into x) ----------------
__global__ void place_k(const void* __restrict__ ei) {
    int e = blockIdx.x * blockDim.x + threadIdx.x;
    if (e >= EE) return;
    int r = edge_val(ei, e);
    int c = edge_val(ei, (long long)EE + e);
    int pos = atomicAdd(&g_cursor[r], 1);
    g_col[pos] = c;
}

// ---------------- fused layer: CSR pull of pre-scaled fp16 features ----------------
// One warp per node; 2 dims per lane.
// mode 0: first layer  (residual from emb fp32; write g_out + x)
// mode 1: middle layer (residual from g_out fp16; write g_out + x)
// mode 2: last layer   (residual from g_out fp16; write fp32 outf*0.25 only)
__global__ void layer_k(int src, const float* __restrict__ emb,
                        float* __restrict__ outf, int mode) {
    int gw = (blockIdx.x * blockDim.x + threadIdx.x) >> 5;
    int lane = threadIdx.x & 31;
    if (gw >= NN) return;

    const __half2* xin = src ? g_x1 : g_x0;
    __half2* xout = src ? g_x0 : g_x1;

    int start = g_rowptr[gw];
    int end = (gw + 1 < NN) ? g_rowptr[gw + 1] : EE;

    float ax = 0.0f, ay = 0.0f;
    for (int base = start; base < end; base += 32) {
        int n = min(32, end - base);
        int col = 0;
        if (lane < n) col = __ldg(&g_col[base + lane]);
        int j = 0;
        for (; j + 4 <= n; j += 4) {
            int c0 = __shfl_sync(0xffffffffu, col, j);
            int c1 = __shfl_sync(0xffffffffu, col, j + 1);
            int c2 = __shfl_sync(0xffffffffu, col, j + 2);
            int c3 = __shfl_sync(0xffffffffu, col, j + 3);
            __half2 h0 = __ldg(&xin[c0 * HD + lane]);
            __half2 h1 = __ldg(&xin[c1 * HD + lane]);
            __half2 h2 = __ldg(&xin[c2 * HD + lane]);
            __half2 h3 = __ldg(&xin[c3 * HD + lane]);
            float2 v0 = __half22float2(h0);
            float2 v1 = __half22float2(h1);
            float2 v2 = __half22float2(h2);
            float2 v3 = __half22float2(h3);
            ax += v0.x + v1.x;  ay += v0.y + v1.y;
            ax += v2.x + v3.x;  ay += v2.y + v3.y;
        }
        for (; j < n; j++) {
            int c = __shfl_sync(0xffffffffu, col, j);
            float2 v = __half22float2(__ldg(&xin[c * HD + lane]));
            ax += v.x;
            ay += v.y;
        }
    }

    float isr = g_invsq[gw];
    ax *= isr;
    ay *= isr;

    int bidx = gw * HD + lane;                 // float2 / half2 index
    float2 o;
    if (mode == 0) o = ((const float2*)emb)[bidx];
    else           o = __half22float2(g_out[bidx]);

    float vx = ax + o.x;
    float vy = ay + o.y;
    float ss = vx * vx + vy * vy;
#pragma unroll
    for (int m = 16; m; m >>= 1) ss += __shfl_xor_sync(0xffffffffu, ss, m);
    float s = 1.0f / fmaxf(sqrtf(ss), 1e-12f);
    vx *= s;
    vy *= s;

    if (mode == 2) {
        ((float2*)outf)[bidx] = make_float2((o.x + vx) * 0.25f, (o.y + vy) * 0.25f);
    } else {
        xout[bidx] = __floats2half2_rn(vx * isr, vy * isr);
        g_out[bidx] = __floats2half2_rn(o.x + vx, o.y + vy);
    }
}

// ---------------- launch (kernel launches ONLY) ----------------
extern "C" void kernel_launch(void* const* d_in, const int* in_sizes, int n_in,
                              void* d_out, int out_size) {
    int ei_idx = 0, emb_idx = 1;
    if (in_sizes[0] == NN * DD) { ei_idx = 1; emb_idx = 0; }
    const void* ei = d_in[ei_idx];
    const float* emb = (const float*)d_in[emb_idx];
    float* out = (float*)d_out;

    initdet_k<<<(NN + 255) / 256, 256>>>((const unsigned*)ei);
    hist_k<<<(EE + 255) / 256, 256>>>(ei);
    scanfused_k<<<NBLK_SCAN, SCAN_CHUNK>>>();
    scale_k<<<(NN * HD + 255) / 256, 256>>>(emb);
    place_k<<<(EE + 255) / 256, 256>>>(ei);

    const int node_blocks = (NN * 32 + 255) / 256;  // 12500
    layer_k<<<node_blocks, 256>>>(0, emb, out, 0);
    layer_k<<<node_blocks, 256>>>(1, emb, out, 1);
    layer_k<<<node_blocks, 256>>>(0, emb, out, 2);
}

// round 13
// speedup vs baseline: 1.0483x; 1.0483x over previous
#include <cuda_runtime.h>
#include <cuda_fp16.h>

#define NN 100000
#define DD 64
#define HD 32   // half2 elements per node row
#define EE 1200000
#define SCAN_CHUNK 1024
#define NBLK_SCAN ((NN + SCAN_CHUNK - 1) / SCAN_CHUNK)  // 98

// ---------------- scratch (static device globals; zero-init at module load) ----------------
__device__ int     g_deg[NN];      // col-degree        (zeroed by cleanup_k each call)
__device__ int     g_cnt[NN];      // row counts        (zeroed by cleanup_k each call)
__device__ int     g_rowptr[NN];   // exclusive scan of g_cnt
__device__ int     g_cursor[NN];   // placement cursors (pre-seeded by scan)
__device__ float   g_invsq[NN];    // rsqrt(max(deg,1))
__device__ int     g_aggr[NBLK_SCAN];          // per-block aggregates
__device__ volatile int g_ready[NBLK_SCAN];    // publish flags (zeroed by cleanup_k)
__device__ int     g_col[EE];      // col only, sorted by row
__device__ __half2 g_x0[NN * HD];  // pre-scaled features: invsq[node]*x[node]
__device__ __half2 g_x1[NN * HD];

// ---------------- per-block dtype self-detection ----------------
// Sample the first 256 odd 32-bit words. For nonneg int64 < 2^31 they are all
// the zero high-halves of row values; for int32 they are 256 random node ids
// (all-zero has probability ~0). Whole block agrees via __syncthreads_and.
__device__ __forceinline__ int block_detect_is64(const unsigned* w) {
    unsigned s = w[((threadIdx.x & 255) << 1) | 1];
    return __syncthreads_and(s == 0u);
}

__device__ __forceinline__ int edge_val(const void* ei, long long idx, int is64) {
    if (is64) return (int)((const long long*)ei)[idx];
    return ((const int*)ei)[idx];
}

// ---------------- launch 0: histograms (col-degree + row counts) ----------------
// Relies on g_deg/g_cnt being zero (module-load init on call 1; cleanup_k after).
__global__ void hist_k(const void* __restrict__ ei) {
    int is64 = block_detect_is64((const unsigned*)ei);
    int e = blockIdx.x * blockDim.x + threadIdx.x;
    if (e >= EE) return;
    int r = edge_val(ei, e, is64);
    int c = edge_val(ei, (long long)EE + e, is64);
    atomicAdd(&g_deg[c], 1);
    atomicAdd(&g_cnt[r], 1);
}

// ---------------- launch 1: fused single-pass scan + invsq + cursor + x0 scale ----
// Decoupled lookback; 98 blocks all co-resident -> polling is deadlock-free.
__global__ void scanscale_k(const float* __restrict__ emb) {
    __shared__ int wsum[32];
    __shared__ int pred[128];
    __shared__ float sinv[SCAN_CHUNK];
    int bid = blockIdx.x;
    int g = bid * SCAN_CHUNK + threadIdx.x;
    int v = (g < NN) ? g_cnt[g] : 0;
    int lane = threadIdx.x & 31, wid = threadIdx.x >> 5;

    // block-local inclusive scan (warp shuffles)
    int x = v;
#pragma unroll
    for (int off = 1; off < 32; off <<= 1) {
        int t = __shfl_up_sync(0xffffffffu, x, off);
        if (lane >= off) x += t;
    }
    if (lane == 31) wsum[wid] = x;
    __syncthreads();
    if (wid == 0) {
        int s = wsum[lane];
#pragma unroll
        for (int off = 1; off < 32; off <<= 1) {
            int t = __shfl_up_sync(0xffffffffu, s, off);
            if (lane >= off) s += t;
        }
        wsum[lane] = s;
    }
    __syncthreads();
    int incl = x + (wid ? wsum[wid - 1] : 0);

    // publish aggregate
    if (threadIdx.x == SCAN_CHUNK - 1) {
        g_aggr[bid] = incl;
        __threadfence();
        g_ready[bid] = 1;
    }

    // parallel lookback over predecessors
    if (threadIdx.x < 128) {
        int a = 0;
        if (threadIdx.x < bid) {
            while (g_ready[threadIdx.x] == 0) { }
            __threadfence();
            a = g_aggr[threadIdx.x];
        }
        pred[threadIdx.x] = a;
    }
    __syncthreads();
    if (threadIdx.x < 64) pred[threadIdx.x] += pred[threadIdx.x + 64];
    __syncthreads();
    if (threadIdx.x < 32) {
        int s = pred[threadIdx.x] + pred[threadIdx.x + 32];
#pragma unroll
        for (int m = 16; m; m >>= 1) s += __shfl_xor_sync(0xffffffffu, s, m);
        if (threadIdx.x == 0) pred[0] = s;
    }
    __syncthreads();
    int offset = pred[0];

    float inv = 0.0f;
    if (g < NN) {
        int p = incl - v + offset;
        g_rowptr[g] = p;
        g_cursor[g] = p;
        inv = rsqrtf(fmaxf((float)g_deg[g], 1.0f));
        g_invsq[g] = inv;
    }
    sinv[threadIdx.x] = inv;
    __syncthreads();

    // scale this block's 1024 nodes: x0 = half(invsq * emb)
    int base = bid * SCAN_CHUNK * HD;              // half2 index of node range start
    int limit = min(NN * HD - base, SCAN_CHUNK * HD);
    for (int i = threadIdx.x; i < limit; i += SCAN_CHUNK) {
        float isr = sinv[i >> 5];
        float2 e = ((const float2*)emb)[base + i];
        g_x0[base + i] = __floats2half2_rn(e.x * isr, e.y * isr);
    }
}

// ---------------- launch 2: place edges into CSR (col only) ----------------
__global__ void place_k(const void* __restrict__ ei) {
    int is64 = block_detect_is64((const unsigned*)ei);
    int e = blockIdx.x * blockDim.x + threadIdx.x;
    if (e >= EE) return;
    int r = edge_val(ei, e, is64);
    int c = edge_val(ei, (long long)EE + e, is64);
    int pos = atomicAdd(&g_cursor[r], 1);
    g_col[pos] = c;
}

// ---------------- launches 3-5: fused layer (CSR pull, fp16 gather, fp32 residual) --
// One warp per node; 2 dims per lane.
// mode 0: residual from emb;  write x + outf
// mode 1: residual from outf; write x + outf
// mode 2: residual from outf; write outf = (o+v)*0.25 only
__global__ void layer_k(int src, const float* __restrict__ emb,
                        float* __restrict__ outf, int mode) {
    int gw = (blockIdx.x * blockDim.x + threadIdx.x) >> 5;
    int lane = threadIdx.x & 31;
    if (gw >= NN) return;

    const __half2* xin = src ? g_x1 : g_x0;
    __half2* xout = src ? g_x0 : g_x1;

    int start = g_rowptr[gw];
    int end = (gw + 1 < NN) ? g_rowptr[gw + 1] : EE;

    float ax = 0.0f, ay = 0.0f;
    for (int base = start; base < end; base += 32) {
        int n = min(32, end - base);
        int col = 0;
        if (lane < n) col = __ldg(&g_col[base + lane]);
        int j = 0;
        for (; j + 4 <= n; j += 4) {
            int c0 = __shfl_sync(0xffffffffu, col, j);
            int c1 = __shfl_sync(0xffffffffu, col, j + 1);
            int c2 = __shfl_sync(0xffffffffu, col, j + 2);
            int c3 = __shfl_sync(0xffffffffu, col, j + 3);
            __half2 h0 = __ldg(&xin[c0 * HD + lane]);
            __half2 h1 = __ldg(&xin[c1 * HD + lane]);
            __half2 h2 = __ldg(&xin[c2 * HD + lane]);
            __half2 h3 = __ldg(&xin[c3 * HD + lane]);
            float2 v0 = __half22float2(h0);
            float2 v1 = __half22float2(h1);
            float2 v2 = __half22float2(h2);
            float2 v3 = __half22float2(h3);
            ax += v0.x + v1.x;  ay += v0.y + v1.y;
            ax += v2.x + v3.x;  ay += v2.y + v3.y;
        }
        for (; j < n; j++) {
            int c = __shfl_sync(0xffffffffu, col, j);
            float2 v = __half22float2(__ldg(&xin[c * HD + lane]));
            ax += v.x;
            ay += v.y;
        }
    }

    float isr = g_invsq[gw];
    ax *= isr;
    ay *= isr;

    int bidx = gw * HD + lane;
    float2 o;
    if (mode == 0) o = ((const float2*)emb)[bidx];
    else           o = ((const float2*)outf)[bidx];

    float vx = ax + o.x;
    float vy = ay + o.y;
    float ss = vx * vx + vy * vy;
#pragma unroll
    for (int m = 16; m; m >>= 1) ss += __shfl_xor_sync(0xffffffffu, ss, m);
    float s = 1.0f / fmaxf(sqrtf(ss), 1e-12f);
    vx *= s;
    vy *= s;

    if (mode == 2) {
        ((float2*)outf)[bidx] = make_float2((o.x + vx) * 0.25f, (o.y + vy) * 0.25f);
    } else {
        xout[bidx] = __floats2half2_rn(vx * isr, vy * isr);
        ((float2*)outf)[bidx] = make_float2(o.x + vx, o.y + vy);
    }
}

// ---------------- launch 6: restore zeroed state for the next call ----------------
__global__ void cleanup_k() {
    int i = blockIdx.x * blockDim.x + threadIdx.x;
    if (i < NN) {
        g_deg[i] = 0;
        g_cnt[i] = 0;
    }
    if (i < NBLK_SCAN) g_ready[i] = 0;
}

// ---------------- launch (kernel launches ONLY) ----------------
extern "C" void kernel_launch(void* const* d_in, const int* in_sizes, int n_in,
                              void* d_out, int out_size) {
    int ei_idx = 0, emb_idx = 1;
    if (in_sizes[0] == NN * DD) { ei_idx = 1; emb_idx = 0; }
    const void* ei = d_in[ei_idx];
    const float* emb = (const float*)d_in[emb_idx];
    float* out = (float*)d_out;

    const int node_blocks = (NN * 32 + 255) / 256;  // 12500

    hist_k<<<(EE + 255) / 256, 256>>>(ei);            // 0
    scanscale_k<<<NBLK_SCAN, SCAN_CHUNK>>>(emb);      // 1
    place_k<<<(EE + 255) / 256, 256>>>(ei);           // 2
    layer_k<<<node_blocks, 256>>>(0, emb, out, 0);    // 3  <- ncu capture slot
    layer_k<<<node_blocks, 256>>>(1, emb, out, 1);    // 4
    layer_k<<<node_blocks, 256>>>(0, emb, out, 2);    // 5
    cleanup_k<<<(NN + 255) / 256, 256>>>();           // 6
}